// round 1
// baseline (speedup 1.0000x reference)
#include <cuda_runtime.h>
#include <math.h>

#define N_NODES 50000
#define N_EDGES 800000
#define NF 256
#define NH 64
#define NC 16

// ---------------- scratch (device globals: no allocation allowed) ----------
__device__ float g_U0[N_NODES * NF];
__device__ float g_U1[N_NODES * NF];
__device__ float g_h [N_NODES * NH];
__device__ float g_y [N_NODES * NH];
__device__ float g_t [N_NODES * NH];
__device__ float g_k1[N_NODES * NH];
__device__ float g_k2[N_NODES * NH];
__device__ float g_k3[N_NODES * NH];
__device__ float g_k4[N_NODES * NH];
__device__ float g_Wcat1[3 * NF * NH];
__device__ float g_WcatA[3 * NH * NH];
__device__ float g_WcatB[3 * NH * NH];
__device__ float g_Wcat2[3 * NH * NC];
__device__ int   g_off[N_NODES + 1];
__device__ int   g_deg[N_NODES];
__device__ int   g_cur[N_NODES];
__device__ int   g_ssrc[N_EDGES];
__device__ float g_sp [N_EDGES];

// ---------------- CSR build ----------------
__global__ void k_zero() {
    int i = blockIdx.x * blockDim.x + threadIdx.x;
    if (i < N_NODES) { g_deg[i] = 0; g_cur[i] = 0; }
}

__global__ void k_hist(const int* __restrict__ dst) {
    int e = blockIdx.x * blockDim.x + threadIdx.x;
    if (e < N_EDGES) atomicAdd(&g_deg[dst[e]], 1);
}

// single block, 1024 threads: chunked exclusive scan of g_deg -> g_off
__global__ void k_scan() {
    __shared__ int sm[1024];
    int t = threadIdx.x;
    const int CH = (N_NODES + 1023) / 1024;
    int base = t * CH;
    int s = 0;
    for (int j = 0; j < CH; j++) {
        int i = base + j;
        if (i < N_NODES) s += g_deg[i];
    }
    sm[t] = s;
    __syncthreads();
    for (int d = 1; d < 1024; d <<= 1) {
        int v = (t >= d) ? sm[t - d] : 0;
        __syncthreads();
        sm[t] += v;
        __syncthreads();
    }
    int run = sm[t] - s;  // exclusive prefix
    for (int j = 0; j < CH; j++) {
        int i = base + j;
        if (i < N_NODES) { g_off[i] = run; run += g_deg[i]; }
    }
    if (t == 1023) g_off[N_NODES] = run;
}

__global__ void k_scatter(const int* __restrict__ src, const int* __restrict__ dst,
                          const float* __restrict__ p) {
    int e = blockIdx.x * blockDim.x + threadIdx.x;
    if (e >= N_EDGES) return;
    int d = dst[e];
    int pos = atomicAdd(&g_cur[d], 1);
    int idx = g_off[d] + pos;
    g_ssrc[idx] = src[e];
    g_sp[idx]   = p[e];
}

// ---------------- concatenated weights: [W0 ; W1-W0 ; R] -------------------
__global__ void k_wcat(const float* __restrict__ W, const float* __restrict__ R,
                       float* __restrict__ out, int Cin, int Cout) {
    int i = blockIdx.x * blockDim.x + threadIdx.x;
    int total = 3 * Cin * Cout;
    if (i >= total) return;
    int k = i / Cout, c = i % Cout;
    float v;
    if (k < Cin)            v = W[k * Cout + c];
    else if (k < 2 * Cin)   v = W[(Cin + (k - Cin)) * Cout + c] - W[(k - Cin) * Cout + c];
    else                    v = R[(k - 2 * Cin) * Cout + c];
    out[i] = v;
}

// ---------------- aggregation: one warp per node ---------------------------
// U0[i] = mean_{e:dst=i} x[src_e] ; U1[i] = mean-weighted p_e * x[src_e]
__global__ void k_agg64(const float* __restrict__ X) {
    int gw   = (blockIdx.x * blockDim.x + threadIdx.x) >> 5;
    int lane = threadIdx.x & 31;
    if (gw >= N_NODES) return;
    int s0 = g_off[gw], s1 = g_off[gw + 1];
    const float2* X2 = (const float2*)X;
    float ax = 0.f, ay = 0.f, bx = 0.f, by = 0.f;
    for (int j = s0; j < s1; j++) {
        int s   = g_ssrc[j];
        float p = g_sp[j];
        float2 v = X2[s * 32 + lane];
        ax += v.x; ay += v.y;
        bx += p * v.x; by += p * v.y;
    }
    float inv = 1.0f / (float)max(s1 - s0, 1);
    ((float2*)g_U0)[gw * 32 + lane] = make_float2(ax * inv, ay * inv);
    ((float2*)g_U1)[gw * 32 + lane] = make_float2(bx * inv, by * inv);
}

__global__ void k_agg256(const float* __restrict__ X) {
    int gw   = (blockIdx.x * blockDim.x + threadIdx.x) >> 5;
    int lane = threadIdx.x & 31;
    if (gw >= N_NODES) return;
    int s0 = g_off[gw], s1 = g_off[gw + 1];
    const float4* X4 = (const float4*)X;
    float4 a0 = make_float4(0, 0, 0, 0), a1 = a0, b0 = a0, b1 = a0;
    for (int j = s0; j < s1; j++) {
        int s   = g_ssrc[j];
        float p = g_sp[j];
        float4 v0 = X4[s * 64 + lane];
        float4 v1 = X4[s * 64 + 32 + lane];
        a0.x += v0.x; a0.y += v0.y; a0.z += v0.z; a0.w += v0.w;
        a1.x += v1.x; a1.y += v1.y; a1.z += v1.z; a1.w += v1.w;
        b0.x += p * v0.x; b0.y += p * v0.y; b0.z += p * v0.z; b0.w += p * v0.w;
        b1.x += p * v1.x; b1.y += p * v1.y; b1.z += p * v1.z; b1.w += p * v1.w;
    }
    float inv = 1.0f / (float)max(s1 - s0, 1);
    float4* U0 = (float4*)g_U0;
    float4* U1 = (float4*)g_U1;
    U0[gw * 64 + lane]      = make_float4(a0.x * inv, a0.y * inv, a0.z * inv, a0.w * inv);
    U0[gw * 64 + 32 + lane] = make_float4(a1.x * inv, a1.y * inv, a1.z * inv, a1.w * inv);
    U1[gw * 64 + lane]      = make_float4(b0.x * inv, b0.y * inv, b0.z * inv, b0.w * inv);
    U1[gw * 64 + 32 + lane] = make_float4(b1.x * inv, b1.y * inv, b1.z * inv, b1.w * inv);
}

// ---------------- GEMM: Y[n,64] = [U0|U1|A2] @ Wcat + bias -----------------
// 128x64 tile, BK=16, 256 threads, 4x8 microtile per thread.
template <int CIN, bool TANH>
__global__ void k_gemm64(const float* __restrict__ A2, const float* __restrict__ W,
                         const float* __restrict__ bias, float* __restrict__ Y) {
    __shared__ __align__(16) float As[16][132];
    __shared__ __align__(16) float Bs[16][64];
    int tid  = threadIdx.x;
    int row0 = blockIdx.x * 128;
    int tx = tid & 7, ty = tid >> 3;      // tx: 8 col-groups of 8, ty: 32 row-groups of 4
    float acc[4][8];
#pragma unroll
    for (int i = 0; i < 4; i++)
#pragma unroll
        for (int j = 0; j < 8; j++) acc[i][j] = bias[tx * 8 + j];
    int c  = tid & 15;
    int rb = tid >> 4;
#pragma unroll 1
    for (int seg = 0; seg < 3; seg++) {
        const float* S    = (seg == 0) ? g_U0 : ((seg == 1) ? g_U1 : A2);
        const float* Wseg = W + seg * CIN * 64;
#pragma unroll 1
        for (int kk = 0; kk < CIN; kk += 16) {
#pragma unroll
            for (int i = 0; i < 8; i++) {
                int r = i * 16 + rb;
                int grow = row0 + r;
                As[c][r] = (grow < N_NODES) ? S[grow * CIN + kk + c] : 0.f;
            }
#pragma unroll
            for (int i = 0; i < 4; i++) {
                int idx = tid + i * 256;
                Bs[idx >> 6][idx & 63] = Wseg[(kk + (idx >> 6)) * 64 + (idx & 63)];
            }
            __syncthreads();
#pragma unroll
            for (int k = 0; k < 16; k++) {
                float4 aa = *(const float4*)&As[k][ty * 4];
                float4 w0 = *(const float4*)&Bs[k][tx * 8];
                float4 w1 = *(const float4*)&Bs[k][tx * 8 + 4];
                float a[4] = {aa.x, aa.y, aa.z, aa.w};
                float b[8] = {w0.x, w0.y, w0.z, w0.w, w1.x, w1.y, w1.z, w1.w};
#pragma unroll
                for (int i = 0; i < 4; i++)
#pragma unroll
                    for (int j = 0; j < 8; j++) acc[i][j] += a[i] * b[j];
            }
            __syncthreads();
        }
    }
#pragma unroll
    for (int i = 0; i < 4; i++) {
        int grow = row0 + ty * 4 + i;
        if (grow < N_NODES) {
#pragma unroll
            for (int j = 0; j < 8; j++) {
                float v = acc[i][j];
                if (TANH) v = tanhf(v);
                Y[grow * 64 + tx * 8 + j] = v;
            }
        }
    }
}

// ---------------- final conv (Cout=16) + tanh + log_softmax ----------------
__global__ void k_gemm16(const float* __restrict__ A2, const float* __restrict__ b2,
                         float* __restrict__ out) {
    __shared__ float Ws[3 * NH * NC];
    for (int i = threadIdx.x; i < 3 * NH * NC; i += blockDim.x) Ws[i] = g_Wcat2[i];
    __syncthreads();
    int row = blockIdx.x * blockDim.x + threadIdx.x;
    if (row >= N_NODES) return;
    float acc[16];
#pragma unroll
    for (int cc = 0; cc < 16; cc++) acc[cc] = b2[cc];
    const float* s0 = &g_U0[row * NH];
    const float* s1 = &g_U1[row * NH];
    const float* s2 = &A2[row * NH];
#pragma unroll 1
    for (int seg = 0; seg < 3; seg++) {
        const float* S  = (seg == 0) ? s0 : ((seg == 1) ? s1 : s2);
        const float* Wg = &Ws[seg * NH * 16];
        for (int k = 0; k < NH; k++) {
            float a = S[k];
            const float4* w4 = (const float4*)&Wg[k * 16];
            float4 w0 = w4[0], w1 = w4[1], w2 = w4[2], w3 = w4[3];
            acc[0]  += a * w0.x; acc[1]  += a * w0.y; acc[2]  += a * w0.z; acc[3]  += a * w0.w;
            acc[4]  += a * w1.x; acc[5]  += a * w1.y; acc[6]  += a * w1.z; acc[7]  += a * w1.w;
            acc[8]  += a * w2.x; acc[9]  += a * w2.y; acc[10] += a * w2.z; acc[11] += a * w2.w;
            acc[12] += a * w3.x; acc[13] += a * w3.y; acc[14] += a * w3.z; acc[15] += a * w3.w;
        }
    }
    float m = -1e30f;
#pragma unroll
    for (int cc = 0; cc < 16; cc++) { acc[cc] = tanhf(acc[cc]); m = fmaxf(m, acc[cc]); }
    float sum = 0.f;
#pragma unroll
    for (int cc = 0; cc < 16; cc++) sum += expf(acc[cc] - m);
    float lse = m + logf(sum);
#pragma unroll
    for (int cc = 0; cc < 16; cc++) out[row * 16 + cc] = acc[cc] - lse;
}

// ---------------- elementwise helpers --------------------------------------
__global__ void k_axpy(float* __restrict__ y, const float* __restrict__ h,
                       const float* __restrict__ k, float c) {
    int i = blockIdx.x * blockDim.x + threadIdx.x;
    if (i < N_NODES * NH) y[i] = h[i] + c * k[i];
}

__global__ void k_comb() {
    int i = blockIdx.x * blockDim.x + threadIdx.x;
    if (i < N_NODES * NH)
        g_y[i] = g_h[i] + 0.5f * (g_k1[i] + 2.f * g_k2[i] + 2.f * g_k3[i] + g_k4[i]);
}

// ---------------- driver ----------------------------------------------------
extern "C" void kernel_launch(void* const* d_in, const int* in_sizes, int n_in,
                              void* d_out, int out_size) {
    const float* x   = (const float*)d_in[0];
    const float* p   = (const float*)d_in[1];
    const int*   src = (const int*)  d_in[2];
    const int*   dst = (const int*)  d_in[3];
    const float* W1  = (const float*)d_in[4];
    const float* R1  = (const float*)d_in[5];
    const float* b1  = (const float*)d_in[6];
    const float* Wa  = (const float*)d_in[7];
    const float* Ra  = (const float*)d_in[8];
    const float* ba  = (const float*)d_in[9];
    const float* Wb  = (const float*)d_in[10];
    const float* Rb  = (const float*)d_in[11];
    const float* bb  = (const float*)d_in[12];
    const float* W2  = (const float*)d_in[13];
    const float* R2  = (const float*)d_in[14];
    const float* b2  = (const float*)d_in[15];
    float* out = (float*)d_out;

    void* tmp;
    float *ph, *py, *pt, *pk1, *pk2, *pk3, *pk4, *pW1c, *pWAc, *pWBc, *pW2c;
    cudaGetSymbolAddress(&tmp, g_h);     ph   = (float*)tmp;
    cudaGetSymbolAddress(&tmp, g_y);     py   = (float*)tmp;
    cudaGetSymbolAddress(&tmp, g_t);     pt   = (float*)tmp;
    cudaGetSymbolAddress(&tmp, g_k1);    pk1  = (float*)tmp;
    cudaGetSymbolAddress(&tmp, g_k2);    pk2  = (float*)tmp;
    cudaGetSymbolAddress(&tmp, g_k3);    pk3  = (float*)tmp;
    cudaGetSymbolAddress(&tmp, g_k4);    pk4  = (float*)tmp;
    cudaGetSymbolAddress(&tmp, g_Wcat1); pW1c = (float*)tmp;
    cudaGetSymbolAddress(&tmp, g_WcatA); pWAc = (float*)tmp;
    cudaGetSymbolAddress(&tmp, g_WcatB); pWBc = (float*)tmp;
    cudaGetSymbolAddress(&tmp, g_Wcat2); pW2c = (float*)tmp;

    const int EB  = (N_EDGES + 255) / 256;
    const int NB  = (N_NODES + 255) / 256;
    const int AB  = (N_NODES * 32 + 255) / 256;   // warp-per-node agg
    const int GB  = (N_NODES + 127) / 128;        // 128-row gemm tiles
    const int VB  = (N_NODES * NH + 255) / 256;   // elementwise

    // CSR build
    k_zero<<<NB, 256>>>();
    k_hist<<<EB, 256>>>(dst);
    k_scan<<<1, 1024>>>();
    k_scatter<<<EB, 256>>>(src, dst, p);

    // concatenated weights
    k_wcat<<<(3 * NF * NH + 255) / 256, 256>>>(W1, R1, pW1c, NF, NH);
    k_wcat<<<(3 * NH * NH + 255) / 256, 256>>>(Wa, Ra, pWAc, NH, NH);
    k_wcat<<<(3 * NH * NH + 255) / 256, 256>>>(Wb, Rb, pWBc, NH, NH);
    k_wcat<<<(3 * NH * NC + 255) / 256, 256>>>(W2, R2, pW2c, NH, NC);

    // conv1 + tanh -> h
    k_agg256<<<AB, 256>>>(x);
    k_gemm64<NF, true><<<GB, 256>>>(x, pW1c, b1, ph);

    // f(y) = conv_b(conv_a(y))
    auto F = [&](const float* in, float* ko) {
        k_agg64<<<AB, 256>>>(in);
        k_gemm64<NH, false><<<GB, 256>>>(in, pWAc, ba, pt);
        k_agg64<<<AB, 256>>>(pt);
        k_gemm64<NH, false><<<GB, 256>>>(pt, pWBc, bb, ko);
    };

    // RK4, T=3: k2=f(h+1.5k1), k3=f(h+1.5k2), k4=f(h+3k3)
    F(ph, pk1);
    k_axpy<<<VB, 256>>>(py, ph, pk1, 1.5f);
    F(py, pk2);
    k_axpy<<<VB, 256>>>(py, ph, pk2, 1.5f);
    F(py, pk3);
    k_axpy<<<VB, 256>>>(py, ph, pk3, 3.0f);
    F(py, pk4);
    k_comb<<<VB, 256>>>();   // g_y = h + 0.5*(k1+2k2+2k3+k4)

    // conv2 + tanh + log_softmax -> out
    k_agg64<<<AB, 256>>>(py);
    k_gemm16<<<NB, 256>>>(py, b2, out);
}